// round 1
// baseline (speedup 1.0000x reference)
#include <cuda_runtime.h>
#include <cuda_bf16.h>
#include <cstddef>

// ---------------------------------------------------------------------------
// GCN 2-layer forward:  relu(Anorm @ (X W1) + b1) -> relu(Anorm @ (H W2) + b2)
// Anorm = D^-1/2 (A + I) D^-1/2 with D = in-degree(dst)+1 (self-loop).
// ---------------------------------------------------------------------------

#define MAXN 20000
#define MAXF 512

__device__ __align__(16) float g_deg[MAXN];
__device__ __align__(16) float g_dinv[MAXN];
__device__ __align__(16) float g_h[(size_t)MAXN * MAXF];
__device__ __align__(16) float g_agg[(size_t)MAXN * MAXF];
__device__ int g_idx64; // 1 if edge_index is int64, 0 if int32

// --- dtype detect: with int64 little-endian data, every odd int32 word is a
// high word of a value < 2^31 -> zero. With int32 data, odd words are random
// node ids in [0, 20000) -> essentially never all zero over 256 samples.
__global__ void detect_kernel(const int* __restrict__ ei, int n_check) {
    if (threadIdx.x == 0 && blockIdx.x == 0) {
        int nz = 0;
        for (int i = 0; i < n_check; i++) nz += (ei[2 * i + 1] != 0);
        g_idx64 = (nz == 0) ? 1 : 0;
    }
}

__global__ void deg_init_kernel(float* __restrict__ deg, int n) {
    int i = blockIdx.x * blockDim.x + threadIdx.x;
    if (i < n) deg[i] = 1.0f; // self-loop
}

__global__ void deg_count_kernel(const void* __restrict__ eiv, float* __restrict__ deg,
                                 long long E) {
    long long i = blockIdx.x * (long long)blockDim.x + threadIdx.x;
    if (i >= E) return;
    int d;
    if (g_idx64) d = (int)((const long long*)eiv)[E + i];
    else         d = ((const int*)eiv)[(size_t)E + i];
    atomicAdd(&deg[d], 1.0f);
}

__global__ void dinv_kernel(const float* __restrict__ deg, float* __restrict__ dinv, int n) {
    int i = blockIdx.x * blockDim.x + threadIdx.x;
    if (i < n) dinv[i] = rsqrtf(deg[i]);
}

// --- tiled fp32 GEMM: C[M,N] = A[M,K] @ B[K,N], row-major. N % 128 == 0,
// K % 16 == 0 (true here: K in {512}, N in {512,256}). M guarded.
#define BM 128
#define BN 128
#define BK 16
#define AS_STRIDE (BM + 4)

__global__ __launch_bounds__(256, 2)
void gemm_kernel(const float* __restrict__ A, const float* __restrict__ B,
                 float* __restrict__ C, int M, int N, int K) {
    __shared__ float As[BK][AS_STRIDE];
    __shared__ float Bs[BK][BN];

    const int tid = threadIdx.x;      // 0..255
    const int tx = tid % 16;          // n
    const int ty = tid / 16;          // m
    const int m0 = blockIdx.x * BM;
    const int n0 = blockIdx.y * BN;

    float acc[8][8];
#pragma unroll
    for (int i = 0; i < 8; i++)
#pragma unroll
        for (int j = 0; j < 8; j++) acc[i][j] = 0.0f;

    const int arow_base = tid / 4;        // 0..63
    const int acol = (tid % 4) * 4;       // 0,4,8,12
    const int brow_base = tid / 32;       // 0..7
    const int bcol = (tid % 32) * 4;      // 0..124

    for (int k0 = 0; k0 < K; k0 += BK) {
#pragma unroll
        for (int r = 0; r < 2; r++) {
            int row = arow_base + 64 * r;
            int grow = m0 + row;
            float4 v = make_float4(0.f, 0.f, 0.f, 0.f);
            if (grow < M)
                v = *(const float4*)(A + (size_t)grow * K + k0 + acol);
            As[acol + 0][row] = v.x;
            As[acol + 1][row] = v.y;
            As[acol + 2][row] = v.z;
            As[acol + 3][row] = v.w;
        }
#pragma unroll
        for (int r = 0; r < 2; r++) {
            int krow = brow_base + 8 * r;
            float4 v = *(const float4*)(B + (size_t)(k0 + krow) * N + n0 + bcol);
            *(float4*)&Bs[krow][bcol] = v;
        }
        __syncthreads();

#pragma unroll
        for (int k = 0; k < BK; k++) {
            float ra[8], rb[8];
#pragma unroll
            for (int i = 0; i < 8; i++) ra[i] = As[k][ty + 16 * i];
#pragma unroll
            for (int j = 0; j < 8; j++) rb[j] = Bs[k][tx + 16 * j];
#pragma unroll
            for (int i = 0; i < 8; i++)
#pragma unroll
                for (int j = 0; j < 8; j++) acc[i][j] += ra[i] * rb[j];
        }
        __syncthreads();
    }

#pragma unroll
    for (int i = 0; i < 8; i++) {
        int grow = m0 + ty + 16 * i;
        if (grow < M) {
#pragma unroll
            for (int j = 0; j < 8; j++)
                C[(size_t)grow * N + n0 + tx + 16 * j] = acc[i][j];
        }
    }
}

// out[i,f] = h[i,f] * dinv[i]^2   (the self-loop contribution, also inits out)
__global__ void self_init_kernel(const float* __restrict__ h, const float* __restrict__ dinv,
                                 float* __restrict__ out, int n, int F) {
    long long i = blockIdx.x * (long long)blockDim.x + threadIdx.x;
    long long total = (long long)n * (F >> 2);
    if (i >= total) return;
    int row = (int)(i / (F >> 2));
    float s = dinv[row];
    s = s * s;
    float4 v = ((const float4*)h)[i];
    v.x *= s; v.y *= s; v.z *= s; v.w *= s;
    ((float4*)out)[i] = v;
}

// one warp per edge: out[dst] += h[src] * dinv[src]*dinv[dst]
__global__ void scatter_kernel(const float* __restrict__ h, const void* __restrict__ eiv,
                               const float* __restrict__ dinv, float* __restrict__ out,
                               long long E, int F) {
    long long gw = (long long)(blockIdx.x * (long long)blockDim.x + threadIdx.x) >> 5;
    int lane = threadIdx.x & 31;
    if (gw >= E) return;
    int s, d;
    if (g_idx64) {
        const long long* ei = (const long long*)eiv;
        s = (int)ei[gw];
        d = (int)ei[E + gw];
    } else {
        const int* ei = (const int*)eiv;
        s = ei[(size_t)gw];
        d = ei[(size_t)E + gw];
    }
    float norm = dinv[s] * dinv[d];
    const float4* hr = (const float4*)(h + (size_t)s * F);
    float* orow = out + (size_t)d * F;
    int nf4 = F >> 2;
    for (int i = lane; i < nf4; i += 32) {
        float4 v = __ldg(hr + i);
        atomicAdd(orow + 4 * i + 0, v.x * norm);
        atomicAdd(orow + 4 * i + 1, v.y * norm);
        atomicAdd(orow + 4 * i + 2, v.z * norm);
        atomicAdd(orow + 4 * i + 3, v.w * norm);
    }
}

// out[i,f] = max(in[i,f] + b[f], 0)
__global__ void bias_relu_kernel(const float* __restrict__ in, const float* __restrict__ b,
                                 float* __restrict__ out, int n, int F) {
    long long i = blockIdx.x * (long long)blockDim.x + threadIdx.x;
    long long total = (long long)n * (F >> 2);
    if (i >= total) return;
    int col4 = (int)(i % (F >> 2));
    float4 bb = ((const float4*)b)[col4];
    float4 v = ((const float4*)in)[i];
    v.x = fmaxf(v.x + bb.x, 0.f);
    v.y = fmaxf(v.y + bb.y, 0.f);
    v.z = fmaxf(v.z + bb.z, 0.f);
    v.w = fmaxf(v.w + bb.w, 0.f);
    ((float4*)out)[i] = v;
}

extern "C" void kernel_launch(void* const* d_in, const int* in_sizes, int n_in,
                              void* d_out, int out_size) {
    const float* x  = (const float*)d_in[0];
    const void*  ei = d_in[1];
    const float* W1 = (const float*)d_in[2];
    const float* b1 = (const float*)d_in[3];
    const float* W2 = (const float*)d_in[4];
    const float* b2 = (const float*)d_in[5];
    float* out = (float*)d_out;

    const int hf   = in_sizes[3];              // 512
    const int inf  = in_sizes[2] / hf;         // 512
    const int ncls = in_sizes[5];              // 256
    const int n    = in_sizes[0] / inf;        // 20000
    const long long E = (long long)in_sizes[1] / 2; // 160000

    float *p_deg, *p_dinv, *p_h, *p_agg;
    cudaGetSymbolAddress((void**)&p_deg, g_deg);
    cudaGetSymbolAddress((void**)&p_dinv, g_dinv);
    cudaGetSymbolAddress((void**)&p_h, g_h);
    cudaGetSymbolAddress((void**)&p_agg, g_agg);

    // degree / normalization
    detect_kernel<<<1, 1>>>((const int*)ei, 256);
    deg_init_kernel<<<(n + 255) / 256, 256>>>(p_deg, n);
    deg_count_kernel<<<(int)((E + 255) / 256), 256>>>(ei, p_deg, E);
    dinv_kernel<<<(n + 255) / 256, 256>>>(p_deg, p_dinv, n);

    // layer 1: h = x @ W1 ; agg = Anorm h ; h = relu(agg + b1)
    {
        dim3 grid((n + BM - 1) / BM, hf / BN);
        gemm_kernel<<<grid, 256>>>(x, W1, p_h, n, hf, inf);
    }
    {
        long long tot4 = (long long)n * (hf >> 2);
        self_init_kernel<<<(int)((tot4 + 255) / 256), 256>>>(p_h, p_dinv, p_agg, n, hf);
        int blocks = (int)((E * 32 + 255) / 256);
        scatter_kernel<<<blocks, 256>>>(p_h, ei, p_dinv, p_agg, E, hf);
        bias_relu_kernel<<<(int)((tot4 + 255) / 256), 256>>>(p_agg, b1, p_h, n, hf);
    }

    // layer 2: h2 = h @ W2 ; out = relu(Anorm h2 + b2)
    {
        dim3 grid((n + BM - 1) / BM, ncls / BN);
        gemm_kernel<<<grid, 256>>>(p_h, W2, p_agg, n, ncls, hf);
    }
    {
        long long tot4 = (long long)n * (ncls >> 2);
        self_init_kernel<<<(int)((tot4 + 255) / 256), 256>>>(p_agg, p_dinv, out, n, ncls);
        int blocks = (int)((E * 32 + 255) / 256);
        scatter_kernel<<<blocks, 256>>>(p_agg, ei, p_dinv, out, E, ncls);
        bias_relu_kernel<<<(int)((tot4 + 255) / 256), 256>>>(out, b2, out, n, ncls);
    }
}

// round 3
// speedup vs baseline: 1.6364x; 1.6364x over previous
#include <cuda_runtime.h>
#include <cuda_bf16.h>
#include <cstddef>

// ---------------------------------------------------------------------------
// GCN 2-layer forward:  relu(Anorm @ (X W1) + b1) -> relu(Anorm @ (H W2) + b2)
// Anorm = D^-1/2 (A + I) D^-1/2,  D = in-degree(dst) + 1.
// Aggregation via CSR-by-dst gather (no float atomics), fused bias+ReLU.
// ---------------------------------------------------------------------------

#define MAXN 20000
#define MAXE 160000
#define MAXF 512

__device__ __align__(16) int   g_cnt[MAXN];
__device__ __align__(16) int   g_cursor[MAXN];
__device__ __align__(16) int   g_off[MAXN + 1];
__device__ __align__(16) int   g_csr_src[MAXE];
__device__ __align__(16) float g_dinv[MAXN];
__device__ __align__(16) float g_h[(size_t)MAXN * MAXF];
__device__ __align__(16) float g_agg[(size_t)MAXN * MAXF];
__device__ int g_idx64; // 1 if edge_index is int64, 0 if int32

// int64 little-endian: every odd int32 word is a high word of a value
// < 2^31 -> zero. int32 data: odd words are random node ids -> nonzero.
__global__ void detect_kernel(const int* __restrict__ ei, int n_check) {
    if (threadIdx.x == 0 && blockIdx.x == 0) {
        int nz = 0;
        for (int i = 0; i < n_check; i++) nz += (ei[2 * i + 1] != 0);
        g_idx64 = (nz == 0) ? 1 : 0;
    }
}

__global__ void init_kernel(int* __restrict__ cnt, int* __restrict__ cur, int n) {
    int i = blockIdx.x * blockDim.x + threadIdx.x;
    if (i < n) { cnt[i] = 0; cur[i] = 0; }
}

__global__ void count_kernel(const void* __restrict__ eiv, int* __restrict__ cnt,
                             long long E) {
    long long i = blockIdx.x * (long long)blockDim.x + threadIdx.x;
    if (i >= E) return;
    int d;
    if (g_idx64) d = (int)((const long long*)eiv)[E + i];
    else         d = ((const int*)eiv)[(size_t)E + i];
    atomicAdd(&cnt[d], 1);
}

__global__ void dinv_kernel(const int* __restrict__ cnt, float* __restrict__ dinv, int n) {
    int i = blockIdx.x * blockDim.x + threadIdx.x;
    if (i < n) dinv[i] = rsqrtf((float)cnt[i] + 1.0f);
}

// single-block exclusive scan of cnt[0..n) -> off[0..n]
__global__ void scan_kernel(const int* __restrict__ cnt, int* __restrict__ off, int n) {
    __shared__ int psum[1024];
    const int T = 1024;
    int t = threadIdx.x;
    int chunk = (n + T - 1) / T;
    int lo = t * chunk, hi = min(lo + chunk, n);
    int s = 0;
    for (int i = lo; i < hi; i++) s += cnt[i];
    psum[t] = s;
    __syncthreads();
    // Hillis-Steele inclusive scan on psum
    for (int d = 1; d < T; d <<= 1) {
        int v = (t >= d) ? psum[t - d] : 0;
        __syncthreads();
        psum[t] += v;
        __syncthreads();
    }
    int run = (t == 0) ? 0 : psum[t - 1]; // exclusive base for this chunk
    for (int i = lo; i < hi; i++) {
        off[i] = run;
        run += cnt[i];
    }
    if (t == T - 1) off[n] = run;
}

__global__ void fill_kernel(const void* __restrict__ eiv, const int* __restrict__ off,
                            int* __restrict__ cur, int* __restrict__ csr, long long E) {
    long long i = blockIdx.x * (long long)blockDim.x + threadIdx.x;
    if (i >= E) return;
    int s, d;
    if (g_idx64) {
        const long long* ei = (const long long*)eiv;
        s = (int)ei[i];
        d = (int)ei[E + i];
    } else {
        const int* ei = (const int*)eiv;
        s = ei[(size_t)i];
        d = ei[(size_t)E + i];
    }
    int pos = off[d] + atomicAdd(&cur[d], 1);
    csr[pos] = s;
}

// --- tiled fp32 GEMM: C[M,N] = A[M,K] @ B[K,N]. N%128==0, K%16==0, M guarded.
#define BM 128
#define BN 128
#define BK 16
#define AS_STRIDE (BM + 4)

__global__ __launch_bounds__(256, 2)
void gemm_kernel(const float* __restrict__ A, const float* __restrict__ B,
                 float* __restrict__ C, int M, int N, int K) {
    __shared__ float As[BK][AS_STRIDE];
    __shared__ float Bs[BK][BN];

    const int tid = threadIdx.x;      // 0..255
    const int tx = tid % 16;          // col quad
    const int ty = tid / 16;          // row quad
    const int m0 = blockIdx.x * BM;
    const int n0 = blockIdx.y * BN;

    float acc[8][8];
#pragma unroll
    for (int i = 0; i < 8; i++)
#pragma unroll
        for (int j = 0; j < 8; j++) acc[i][j] = 0.0f;

    const int arow_base = tid / 4;        // 0..63
    const int acol = (tid % 4) * 4;       // 0,4,8,12
    const int brow_base = tid / 32;       // 0..7
    const int bcol = (tid % 32) * 4;      // 0..124

    for (int k0 = 0; k0 < K; k0 += BK) {
#pragma unroll
        for (int r = 0; r < 2; r++) {
            int row = arow_base + 64 * r;
            int grow = m0 + row;
            float4 v = make_float4(0.f, 0.f, 0.f, 0.f);
            if (grow < M)
                v = *(const float4*)(A + (size_t)grow * K + k0 + acol);
            As[acol + 0][row] = v.x;
            As[acol + 1][row] = v.y;
            As[acol + 2][row] = v.z;
            As[acol + 3][row] = v.w;
        }
#pragma unroll
        for (int r = 0; r < 2; r++) {
            int krow = brow_base + 8 * r;
            float4 v = *(const float4*)(B + (size_t)(k0 + krow) * N + n0 + bcol);
            *(float4*)&Bs[krow][bcol] = v;
        }
        __syncthreads();

#pragma unroll
        for (int k = 0; k < BK; k++) {
            // 4x4 quad thread tile: rows ty*4..+3 (+64), cols tx*4..+3 (+64)
            float4 a0 = *(const float4*)&As[k][ty * 4];
            float4 a1 = *(const float4*)&As[k][ty * 4 + 64];
            float4 b0 = *(const float4*)&Bs[k][tx * 4];
            float4 b1 = *(const float4*)&Bs[k][tx * 4 + 64];
            const float ra[8] = {a0.x, a0.y, a0.z, a0.w, a1.x, a1.y, a1.z, a1.w};
            const float rb[8] = {b0.x, b0.y, b0.z, b0.w, b1.x, b1.y, b1.z, b1.w};
#pragma unroll
            for (int i = 0; i < 8; i++)
#pragma unroll
                for (int j = 0; j < 8; j++) acc[i][j] += ra[i] * rb[j];
        }
        __syncthreads();
    }

#pragma unroll
    for (int i = 0; i < 8; i++) {
        int grow = m0 + ty * 4 + (i & 3) + (i >> 2) * 64;
        if (grow < M) {
            float4 v0 = make_float4(acc[i][0], acc[i][1], acc[i][2], acc[i][3]);
            float4 v1 = make_float4(acc[i][4], acc[i][5], acc[i][6], acc[i][7]);
            *(float4*)(C + (size_t)grow * N + n0 + tx * 4) = v0;
            *(float4*)(C + (size_t)grow * N + n0 + tx * 4 + 64) = v1;
        }
    }
}

// fused aggregation: out[d] = relu(dinv[d] * (sum_e dinv[src]*h[src] + dinv[d]*h[d]) + b)
// one block per dst node, blockDim.x = F/4 threads (float4 per thread)
__global__ void gather_kernel(const float* __restrict__ h, const int* __restrict__ csr,
                              const int* __restrict__ off, const float* __restrict__ dinv,
                              const float* __restrict__ bias, float* __restrict__ out,
                              int F) {
    int d = blockIdx.x;
    int c = threadIdx.x; // float4 column index
    float di = dinv[d];
    int e0 = off[d], e1 = off[d + 1];

    const float4* hrow = (const float4*)(h + (size_t)d * F);
    float4 acc = hrow[c];
    acc.x *= di; acc.y *= di; acc.z *= di; acc.w *= di;

    for (int e = e0; e < e1; e++) {
        int s = csr[e];
        float ns = dinv[s];
        float4 v = __ldg((const float4*)(h + (size_t)s * F) + c);
        acc.x += ns * v.x; acc.y += ns * v.y; acc.z += ns * v.z; acc.w += ns * v.w;
    }
    float4 bb = ((const float4*)bias)[c];
    acc.x = fmaxf(acc.x * di + bb.x, 0.f);
    acc.y = fmaxf(acc.y * di + bb.y, 0.f);
    acc.z = fmaxf(acc.z * di + bb.z, 0.f);
    acc.w = fmaxf(acc.w * di + bb.w, 0.f);
    ((float4*)(out + (size_t)d * F))[c] = acc;
}

extern "C" void kernel_launch(void* const* d_in, const int* in_sizes, int n_in,
                              void* d_out, int out_size) {
    const float* x  = (const float*)d_in[0];
    const void*  ei = d_in[1];
    const float* W1 = (const float*)d_in[2];
    const float* b1 = (const float*)d_in[3];
    const float* W2 = (const float*)d_in[4];
    const float* b2 = (const float*)d_in[5];
    float* out = (float*)d_out;

    const int hf   = in_sizes[3];                   // 512
    const int inf  = in_sizes[2] / hf;              // 512
    const int ncls = in_sizes[5];                   // 256
    const int n    = in_sizes[0] / inf;             // 20000
    const long long E = (long long)in_sizes[1] / 2; // 160000

    int *p_cnt, *p_cur, *p_off, *p_csr;
    float *p_dinv, *p_h, *p_agg;
    cudaGetSymbolAddress((void**)&p_cnt, g_cnt);
    cudaGetSymbolAddress((void**)&p_cur, g_cursor);
    cudaGetSymbolAddress((void**)&p_off, g_off);
    cudaGetSymbolAddress((void**)&p_csr, g_csr_src);
    cudaGetSymbolAddress((void**)&p_dinv, g_dinv);
    cudaGetSymbolAddress((void**)&p_h, g_h);
    cudaGetSymbolAddress((void**)&p_agg, g_agg);

    // launches 1..5 (graph prep), 6 = gemm1 (ncu -s 5 captures this one)
    detect_kernel<<<1, 1>>>((const int*)ei, 256);                       // 1
    init_kernel<<<(n + 255) / 256, 256>>>(p_cnt, p_cur, n);             // 2
    count_kernel<<<(int)((E + 255) / 256), 256>>>(ei, p_cnt, E);        // 3
    dinv_kernel<<<(n + 255) / 256, 256>>>(p_cnt, p_dinv, n);            // 4
    scan_kernel<<<1, 1024>>>(p_cnt, p_off, n);                          // 5

    {
        dim3 grid((n + BM - 1) / BM, hf / BN);
        gemm_kernel<<<grid, 256>>>(x, W1, p_h, n, hf, inf);             // 6
    }
    fill_kernel<<<(int)((E + 255) / 256), 256>>>(ei, p_off, p_cur, p_csr, E); // 7
    gather_kernel<<<n, hf / 4>>>(p_h, p_csr, p_off, p_dinv, b1, p_agg, hf);   // 8

    {
        dim3 grid((n + BM - 1) / BM, ncls / BN);
        gemm_kernel<<<grid, 256>>>(p_agg, W2, p_h, n, ncls, hf);        // 9
    }
    gather_kernel<<<n, ncls / 4>>>(p_h, p_csr, p_off, p_dinv, b2, out, ncls); // 10
}

// round 6
// speedup vs baseline: 2.5130x; 1.5357x over previous
#include <cuda_runtime.h>
#include <cuda_bf16.h>
#include <cstdint>
#include <cstddef>

// ---------------------------------------------------------------------------
// GCN 2-layer forward:  relu(Anorm @ (X W1) + b1) -> relu(Anorm @ (H W2) + b2)
// Anorm = D^-1/2 (A + I) D^-1/2,  D = in-degree(dst) + 1.
// GEMMs via mma.sync bf16 (HMMA) with 2-term hi/lo split (3 products) for
// ~fp32 precision. Aggregation via CSR-by-dst gather, fused bias+ReLU.
// ---------------------------------------------------------------------------

#define MAXN 20000
#define MAXE 160000
#define MAXF 512

__device__ __align__(16) int   g_cnt[MAXN];
__device__ __align__(16) int   g_cursor[MAXN];
__device__ __align__(16) int   g_off[MAXN + 1];
__device__ __align__(16) int   g_csr_src[MAXE];
__device__ __align__(16) float g_dinv[MAXN];
__device__ __align__(16) float g_h[(size_t)MAXN * MAXF];     // gemm1 out (fp32)
__device__ __align__(16) float g_agg[(size_t)MAXN * 256];    // gemm2 out (fp32)
__device__ __align__(16) __nv_bfloat16 g_xhi[(size_t)MAXN * MAXF];
__device__ __align__(16) __nv_bfloat16 g_xlo[(size_t)MAXN * MAXF];
__device__ __align__(16) __nv_bfloat16 g_hhi[(size_t)MAXN * MAXF];
__device__ __align__(16) __nv_bfloat16 g_hlo[(size_t)MAXN * MAXF];
__device__ __align__(16) __nv_bfloat16 g_w1thi[MAXF * MAXF];  // [N][K]
__device__ __align__(16) __nv_bfloat16 g_w1tlo[MAXF * MAXF];
__device__ __align__(16) __nv_bfloat16 g_w2thi[256 * MAXF];
__device__ __align__(16) __nv_bfloat16 g_w2tlo[256 * MAXF];
__device__ int g_idx64;

// ---------------------------------------------------------------- helpers
__device__ __forceinline__ void split_bf16(float v, __nv_bfloat16& hi, __nv_bfloat16& lo) {
    hi = __float2bfloat16_rn(v);
    lo = __float2bfloat16_rn(v - __bfloat162float(hi));
}

// ---------------------------------------------------------------- prep
__global__ void detect_kernel(const int* __restrict__ ei, int n_check) {
    if (threadIdx.x == 0 && blockIdx.x == 0) {
        int nz = 0;
        for (int i = 0; i < n_check; i++) nz += (ei[2 * i + 1] != 0);
        g_idx64 = (nz == 0) ? 1 : 0;
    }
}

__global__ void init_kernel(int* __restrict__ cnt, int* __restrict__ cur, int n) {
    int i = blockIdx.x * blockDim.x + threadIdx.x;
    if (i < n) { cnt[i] = 0; cur[i] = 0; }
}

// blocks [0, eb): degree count.  blocks [eb, ...): split x -> xhi/xlo.
__global__ void count_splitx_kernel(const void* __restrict__ eiv, int* __restrict__ cnt,
                                    const float* __restrict__ x,
                                    __nv_bfloat16* __restrict__ xhi,
                                    __nv_bfloat16* __restrict__ xlo,
                                    long long E, long long nxf4, int eb) {
    if (blockIdx.x < eb) {
        long long i = blockIdx.x * (long long)blockDim.x + threadIdx.x;
        if (i >= E) return;
        int d;
        if (g_idx64) d = (int)((const long long*)eiv)[E + i];
        else         d = ((const int*)eiv)[(size_t)E + i];
        atomicAdd(&cnt[d], 1);
    } else {
        long long i = (blockIdx.x - eb) * (long long)blockDim.x + threadIdx.x;
        if (i >= nxf4) return;
        float4 v = ((const float4*)x)[i];
        __nv_bfloat16 hx, lx, hy, ly, hz, lz, hw, lw;
        split_bf16(v.x, hx, lx); split_bf16(v.y, hy, ly);
        split_bf16(v.z, hz, lz); split_bf16(v.w, hw, lw);
        __nv_bfloat162* ph = (__nv_bfloat162*)xhi + 2 * i;
        __nv_bfloat162* pl = (__nv_bfloat162*)xlo + 2 * i;
        ph[0] = __nv_bfloat162(hx, hy); ph[1] = __nv_bfloat162(hz, hw);
        pl[0] = __nv_bfloat162(lx, ly); pl[1] = __nv_bfloat162(lz, lw);
    }
}

// single-block scan cnt -> off, plus dinv.
__global__ void scan_dinv_kernel(const int* __restrict__ cnt, int* __restrict__ off,
                                 float* __restrict__ dinv, int n) {
    __shared__ int psum[1024];
    const int T = 1024;
    int t = threadIdx.x;
    int chunk = (n + T - 1) / T;
    int lo = t * chunk, hi = min(lo + chunk, n);
    int s = 0;
    for (int i = lo; i < hi; i++) {
        s += cnt[i];
        dinv[i] = rsqrtf((float)cnt[i] + 1.0f);
    }
    psum[t] = s;
    __syncthreads();
    for (int d = 1; d < T; d <<= 1) {
        int v = (t >= d) ? psum[t - d] : 0;
        __syncthreads();
        psum[t] += v;
        __syncthreads();
    }
    int run = (t == 0) ? 0 : psum[t - 1];
    for (int i = lo; i < hi; i++) { off[i] = run; run += cnt[i]; }
    if (t == T - 1) off[n] = run;
}

// blocks [0,eb): CSR fill. [eb, eb+w1b): W1 transpose-split. rest: W2.
__global__ void fill_splitw_kernel(const void* __restrict__ eiv, const int* __restrict__ off,
                                   int* __restrict__ cur, int* __restrict__ csr,
                                   const float* __restrict__ W1,
                                   __nv_bfloat16* __restrict__ w1thi, __nv_bfloat16* __restrict__ w1tlo,
                                   const float* __restrict__ W2,
                                   __nv_bfloat16* __restrict__ w2thi, __nv_bfloat16* __restrict__ w2tlo,
                                   long long E, int eb, int w1b,
                                   int K1, int N1, int N2) {
    if (blockIdx.x < eb) {
        long long i = blockIdx.x * (long long)blockDim.x + threadIdx.x;
        if (i >= E) return;
        int s, d;
        if (g_idx64) {
            const long long* ei = (const long long*)eiv;
            s = (int)ei[i]; d = (int)ei[E + i];
        } else {
            const int* ei = (const int*)eiv;
            s = ei[(size_t)i]; d = ei[(size_t)E + i];
        }
        int pos = off[d] + atomicAdd(&cur[d], 1);
        csr[pos] = s;
    } else if (blockIdx.x < eb + w1b) {
        int e = (blockIdx.x - eb) * blockDim.x + threadIdx.x;
        if (e >= K1 * N1) return;
        int k = e / N1, nn = e % N1;
        __nv_bfloat16 h, l;
        split_bf16(W1[e], h, l);
        w1thi[(size_t)nn * K1 + k] = h;
        w1tlo[(size_t)nn * K1 + k] = l;
    } else {
        int e = (blockIdx.x - eb - w1b) * blockDim.x + threadIdx.x;
        if (e >= K1 * N2) return;
        int k = e / N2, nn = e % N2;
        __nv_bfloat16 h, l;
        split_bf16(W2[e], h, l);
        w2thi[(size_t)nn * K1 + k] = h;
        w2tlo[(size_t)nn * K1 + k] = l;
    }
}

// ---------------------------------------------------------------- HMMA GEMM
// C[M,Ntot] = A[M,K] @ Bt[Ntot,K]^T.  A,Bt given as bf16 hi/lo pairs.
// CTA tile 128x128, BK=32, 8 warps (warp tile 32x64), cp.async double buffer.
// Smem rows padded to 40 bf16 (80 B stride -> conflict-free ldmatrix).

#define SKP 40                     // padded row stride (bf16)
#define TILE_ELE (128 * SKP)       // one 128x32 tile (padded), in bf16
#define STAGE_ELE (4 * TILE_ELE)   // Ahi,Alo,Bhi,Blo
#define GEMM_SMEM_BYTES (2 * STAGE_ELE * 2)

__device__ __forceinline__ uint32_t smem_cast(const void* p) {
    return (uint32_t)__cvta_generic_to_shared(p);
}
__device__ __forceinline__ void cp16(uint32_t dst, const void* src) {
    asm volatile("cp.async.cg.shared.global [%0], [%1], 16;" :: "r"(dst), "l"(src));
}
__device__ __forceinline__ void ldm_x4(uint32_t* r, uint32_t addr) {
    asm volatile("ldmatrix.sync.aligned.m8n8.x4.shared.b16 {%0,%1,%2,%3}, [%4];"
                 : "=r"(r[0]), "=r"(r[1]), "=r"(r[2]), "=r"(r[3]) : "r"(addr));
}
// B fragment: b0 = same-n k0-7, b1 = same-n k8-15 (non-contiguous in ldm regs!)
__device__ __forceinline__ void mma16816(float* c, const uint32_t* a,
                                         uint32_t b0, uint32_t b1) {
    asm volatile(
        "mma.sync.aligned.m16n8k16.row.col.f32.bf16.bf16.f32 "
        "{%0,%1,%2,%3}, {%4,%5,%6,%7}, {%8,%9}, {%0,%1,%2,%3};"
        : "+f"(c[0]), "+f"(c[1]), "+f"(c[2]), "+f"(c[3])
        : "r"(a[0]), "r"(a[1]), "r"(a[2]), "r"(a[3]), "r"(b0), "r"(b1));
}

extern __shared__ __nv_bfloat16 dynsmem[];

__global__ __launch_bounds__(256)
void gemm_tc_kernel(const __nv_bfloat16* __restrict__ Ahi, const __nv_bfloat16* __restrict__ Alo,
                    const __nv_bfloat16* __restrict__ Bhi, const __nv_bfloat16* __restrict__ Blo,
                    float* __restrict__ C, int M, int Ntot, int K) {
    const int tid = threadIdx.x;
    const int wid = tid >> 5;
    const int lane = tid & 31;
    const int m0 = blockIdx.x * 128;
    const int n0 = blockIdx.y * 128;
    const int wm = (wid & 3) * 32;   // warp m offset in tile
    const int wn = (wid >> 2) * 64;  // warp n offset in tile

    float acc[2][8][4];
#pragma unroll
    for (int i = 0; i < 2; i++)
#pragma unroll
        for (int j = 0; j < 8; j++)
#pragma unroll
            for (int q = 0; q < 4; q++) acc[i][j][q] = 0.0f;

    // cp.async issue for stage st (k block ks*32)
    auto issue_stage = [&](int st, int ks) {
        __nv_bfloat16* base = dynsmem + st * STAGE_ELE;
        const int row = tid >> 1;          // 0..127
        const int ch = (tid & 1);
        const long long kofs = (long long)ks * 32;
        int ga = m0 + row; if (ga >= M) ga = M - 1;  // clamp: garbage rows discarded
        const long long aoff = (long long)ga * K + kofs;
        const long long boff = (long long)(n0 + row) * K + kofs;
        uint32_t drow = smem_cast(base) + (row * SKP) * 2;
#pragma unroll
        for (int c = 0; c < 2; c++) {
            int kk = (ch * 2 + c) * 8;
            cp16(drow + kk * 2,                          Ahi + aoff + kk);
            cp16(drow + (TILE_ELE + kk) * 2,             Alo + aoff + kk);
            cp16(drow + (2 * TILE_ELE + kk) * 2,         Bhi + boff + kk);
            cp16(drow + (3 * TILE_ELE + kk) * 2,         Blo + boff + kk);
        }
        asm volatile("cp.async.commit_group;" ::: "memory");
    };

    const int nsteps = K >> 5; // BK = 32
    issue_stage(0, 0);

    for (int s = 0; s < nsteps; s++) {
        if (s + 1 < nsteps) {
            issue_stage((s + 1) & 1, s + 1);
            asm volatile("cp.async.wait_group 1;" ::: "memory");
        } else {
            asm volatile("cp.async.wait_group 0;" ::: "memory");
        }
        __syncthreads();

        __nv_bfloat16* base = dynsmem + (s & 1) * STAGE_ELE;
        const uint32_t sAhi = smem_cast(base);
        const uint32_t sAlo = sAhi + TILE_ELE * 2;
        const uint32_t sBhi = sAhi + 2 * TILE_ELE * 2;
        const uint32_t sBlo = sAhi + 3 * TILE_ELE * 2;

#pragma unroll
        for (int k16 = 0; k16 < 2; k16++) {
            const int kc = k16 * 16 + ((lane >> 4) * 8);   // ldmatrix col
            const int lr = lane & 15;                       // ldmatrix row sel

            uint32_t ahi[2][4], alo[2][4];
#pragma unroll
            for (int mf = 0; mf < 2; mf++) {
                uint32_t off = ((wm + mf * 16 + lr) * SKP + kc) * 2;
                ldm_x4(ahi[mf], sAhi + off);
                ldm_x4(alo[mf], sAlo + off);
            }
#pragma unroll
            for (int nf2 = 0; nf2 < 4; nf2++) {
                uint32_t off = ((wn + nf2 * 16 + lr) * SKP + kc) * 2;
                uint32_t bhi[4], blo[4];
                ldm_x4(bhi, sBhi + off);
                ldm_x4(blo, sBlo + off);
                // r0={n0-7,k0-7} r1={n8-15,k0-7} r2={n0-7,k8-15} r3={n8-15,k8-15}
                // => n0-7 uses (r0,r2); n8-15 uses (r1,r3)
#pragma unroll
                for (int mf = 0; mf < 2; mf++) {
                    mma16816(acc[mf][2 * nf2 + 0], ahi[mf], bhi[0], bhi[2]);
                    mma16816(acc[mf][2 * nf2 + 1], ahi[mf], bhi[1], bhi[3]);
                    mma16816(acc[mf][2 * nf2 + 0], ahi[mf], blo[0], blo[2]);
                    mma16816(acc[mf][2 * nf2 + 1], ahi[mf], blo[1], blo[3]);
                    mma16816(acc[mf][2 * nf2 + 0], alo[mf], bhi[0], bhi[2]);
                    mma16816(acc[mf][2 * nf2 + 1], alo[mf], bhi[1], bhi[3]);
                }
            }
        }
        __syncthreads();
    }

    // epilogue: c{0,1} -> row group, cols 2t..2t+1 ; c{2,3} -> row group+8
    const int group = lane >> 2;
    const int tq = lane & 3;
#pragma unroll
    for (int mf = 0; mf < 2; mf++) {
#pragma unroll
        for (int nf = 0; nf < 8; nf++) {
            int col = n0 + wn + nf * 8 + tq * 2;
            int r0 = m0 + wm + mf * 16 + group;
            if (r0 < M) {
                float2 v = make_float2(acc[mf][nf][0], acc[mf][nf][1]);
                *(float2*)(C + (size_t)r0 * Ntot + col) = v;
            }
            int r1 = r0 + 8;
            if (r1 < M) {
                float2 v = make_float2(acc[mf][nf][2], acc[mf][nf][3]);
                *(float2*)(C + (size_t)r1 * Ntot + col) = v;
            }
        }
    }
}

// ---------------------------------------------------------------- aggregation
// layer-1: out = relu(dinv[d]*(sum + dinv[d]*h[d]) + b), write bf16 hi/lo split.
__global__ void gather_split_kernel(const float* __restrict__ h, const int* __restrict__ csr,
                                    const int* __restrict__ off, const float* __restrict__ dinv,
                                    const float* __restrict__ bias,
                                    __nv_bfloat16* __restrict__ ohi,
                                    __nv_bfloat16* __restrict__ olo, int F) {
    int d = blockIdx.x;
    int c = threadIdx.x;
    float di = dinv[d];
    int e0 = off[d], e1 = off[d + 1];

    float4 acc = ((const float4*)(h + (size_t)d * F))[c];
    acc.x *= di; acc.y *= di; acc.z *= di; acc.w *= di;
    for (int e = e0; e < e1; e++) {
        int s = csr[e];
        float ns = dinv[s];
        float4 v = __ldg((const float4*)(h + (size_t)s * F) + c);
        acc.x += ns * v.x; acc.y += ns * v.y; acc.z += ns * v.z; acc.w += ns * v.w;
    }
    float4 bb = ((const float4*)bias)[c];
    acc.x = fmaxf(acc.x * di + bb.x, 0.f);
    acc.y = fmaxf(acc.y * di + bb.y, 0.f);
    acc.z = fmaxf(acc.z * di + bb.z, 0.f);
    acc.w = fmaxf(acc.w * di + bb.w, 0.f);

    __nv_bfloat16 hx, lx, hy, ly, hz, lz, hw, lw;
    split_bf16(acc.x, hx, lx); split_bf16(acc.y, hy, ly);
    split_bf16(acc.z, hz, lz); split_bf16(acc.w, hw, lw);
    size_t base2 = ((size_t)d * F) / 2 + 2 * c;
    ((__nv_bfloat162*)ohi)[base2 + 0] = __nv_bfloat162(hx, hy);
    ((__nv_bfloat162*)ohi)[base2 + 1] = __nv_bfloat162(hz, hw);
    ((__nv_bfloat162*)olo)[base2 + 0] = __nv_bfloat162(lx, ly);
    ((__nv_bfloat162*)olo)[base2 + 1] = __nv_bfloat162(lz, lw);
}

// layer-2: plain fp32 output
__global__ void gather_kernel(const float* __restrict__ h, const int* __restrict__ csr,
                              const int* __restrict__ off, const float* __restrict__ dinv,
                              const float* __restrict__ bias, float* __restrict__ out, int F) {
    int d = blockIdx.x;
    int c = threadIdx.x;
    float di = dinv[d];
    int e0 = off[d], e1 = off[d + 1];

    float4 acc = ((const float4*)(h + (size_t)d * F))[c];
    acc.x *= di; acc.y *= di; acc.z *= di; acc.w *= di;
    for (int e = e0; e < e1; e++) {
        int s = csr[e];
        float ns = dinv[s];
        float4 v = __ldg((const float4*)(h + (size_t)s * F) + c);
        acc.x += ns * v.x; acc.y += ns * v.y; acc.z += ns * v.z; acc.w += ns * v.w;
    }
    float4 bb = ((const float4*)bias)[c];
    acc.x = fmaxf(acc.x * di + bb.x, 0.f);
    acc.y = fmaxf(acc.y * di + bb.y, 0.f);
    acc.z = fmaxf(acc.z * di + bb.z, 0.f);
    acc.w = fmaxf(acc.w * di + bb.w, 0.f);
    ((float4*)(out + (size_t)d * F))[c] = acc;
}

// ---------------------------------------------------------------- launch
extern "C" void kernel_launch(void* const* d_in, const int* in_sizes, int n_in,
                              void* d_out, int out_size) {
    const float* x  = (const float*)d_in[0];
    const void*  ei = d_in[1];
    const float* W1 = (const float*)d_in[2];
    const float* b1 = (const float*)d_in[3];
    const float* W2 = (const float*)d_in[4];
    const float* b2 = (const float*)d_in[5];
    float* out = (float*)d_out;

    const int hf   = in_sizes[3];                   // 512
    const int inf  = in_sizes[2] / hf;              // 512
    const int ncls = in_sizes[5];                   // 256
    const int n    = in_sizes[0] / inf;             // 20000
    const long long E = (long long)in_sizes[1] / 2; // 160000

    int *p_cnt, *p_cur, *p_off, *p_csr;
    float *p_dinv, *p_h, *p_agg;
    __nv_bfloat16 *p_xhi, *p_xlo, *p_hhi, *p_hlo, *p_w1hi, *p_w1lo, *p_w2hi, *p_w2lo;
    cudaGetSymbolAddress((void**)&p_cnt, g_cnt);
    cudaGetSymbolAddress((void**)&p_cur, g_cursor);
    cudaGetSymbolAddress((void**)&p_off, g_off);
    cudaGetSymbolAddress((void**)&p_csr, g_csr_src);
    cudaGetSymbolAddress((void**)&p_dinv, g_dinv);
    cudaGetSymbolAddress((void**)&p_h, g_h);
    cudaGetSymbolAddress((void**)&p_agg, g_agg);
    cudaGetSymbolAddress((void**)&p_xhi, g_xhi);
    cudaGetSymbolAddress((void**)&p_xlo, g_xlo);
    cudaGetSymbolAddress((void**)&p_hhi, g_hhi);
    cudaGetSymbolAddress((void**)&p_hlo, g_hlo);
    cudaGetSymbolAddress((void**)&p_w1hi, g_w1thi);
    cudaGetSymbolAddress((void**)&p_w1lo, g_w1tlo);
    cudaGetSymbolAddress((void**)&p_w2hi, g_w2thi);
    cudaGetSymbolAddress((void**)&p_w2lo, g_w2tlo);

    cudaFuncSetAttribute(gemm_tc_kernel, cudaFuncAttributeMaxDynamicSharedMemorySize,
                         GEMM_SMEM_BYTES);

    const int eb = (int)((E + 255) / 256);
    const long long nxf4 = (long long)n * inf / 4;
    const int xb = (int)((nxf4 + 255) / 256);
    const int w1b = (inf * hf + 255) / 256;
    const int w2b = (hf * ncls + 255) / 256;

    detect_kernel<<<1, 1>>>((const int*)ei, 256);                              // 1
    init_kernel<<<(n + 255) / 256, 256>>>(p_cnt, p_cur, n);                    // 2
    count_splitx_kernel<<<eb + xb, 256>>>(ei, p_cnt, x, p_xhi, p_xlo,
                                          E, nxf4, eb);                        // 3
    scan_dinv_kernel<<<1, 1024>>>(p_cnt, p_off, p_dinv, n);                    // 4
    fill_splitw_kernel<<<eb + w1b + w2b, 256>>>(ei, p_off, p_cur, p_csr,
                                                W1, p_w1hi, p_w1lo,
                                                W2, p_w2hi, p_w2lo,
                                                E, eb, w1b, inf, hf, ncls);    // 5
    {
        dim3 grid((n + 127) / 128, hf / 128);
        gemm_tc_kernel<<<grid, 256, GEMM_SMEM_BYTES>>>(p_xhi, p_xlo, p_w1hi, p_w1lo,
                                                       p_h, n, hf, inf);       // 6
    }
    gather_split_kernel<<<n, hf / 4>>>(p_h, p_csr, p_off, p_dinv, b1,
                                       p_hhi, p_hlo, hf);                      // 7
    {
        dim3 grid((n + 127) / 128, ncls / 128);
        gemm_tc_kernel<<<grid, 256, GEMM_SMEM_BYTES>>>(p_hhi, p_hlo, p_w2hi, p_w2lo,
                                                       p_agg, n, ncls, hf);    // 8
    }
    gather_kernel<<<n, ncls / 4>>>(p_agg, p_csr, p_off, p_dinv, b2,
                                   out, ncls);                                 // 9
}

// round 8
// speedup vs baseline: 2.6969x; 1.0732x over previous
#include <cuda_runtime.h>
#include <cuda_bf16.h>
#include <cstdint>
#include <cstddef>

// ---------------------------------------------------------------------------
// GCN 2-layer forward:  relu(Anorm @ (X W1) + b1) -> relu(Anorm @ (H W2) + b2)
// Anorm = D^-1/2 (A + I) D^-1/2,  D = in-degree(dst) + 1.
// GEMMs via mma.sync bf16 (HMMA) with 2-term hi/lo split (3 products) for
// ~fp32 precision. Aggregation via CSR-by-dst gather, fused bias+ReLU.
// ---------------------------------------------------------------------------

#define MAXN 20000
#define MAXE 160000
#define MAXF 512

__device__ __align__(16) int   g_cnt[MAXN];
__device__ __align__(16) int   g_cursor[MAXN];
__device__ __align__(16) int   g_off[MAXN + 1];
__device__ __align__(16) int   g_csr_src[MAXE];
__device__ __align__(16) float g_dinv[MAXN];
__device__ __align__(16) float g_h[(size_t)MAXN * MAXF];     // gemm1 out (fp32)
__device__ __align__(16) float g_agg[(size_t)MAXN * 256];    // gemm2 out (fp32)
__device__ __align__(16) __nv_bfloat16 g_xhi[(size_t)MAXN * MAXF];
__device__ __align__(16) __nv_bfloat16 g_xlo[(size_t)MAXN * MAXF];
__device__ __align__(16) __nv_bfloat16 g_hhi[(size_t)MAXN * MAXF];
__device__ __align__(16) __nv_bfloat16 g_hlo[(size_t)MAXN * MAXF];
__device__ __align__(16) __nv_bfloat16 g_w1thi[MAXF * MAXF];  // [N][K]
__device__ __align__(16) __nv_bfloat16 g_w1tlo[MAXF * MAXF];
__device__ __align__(16) __nv_bfloat16 g_w2thi[256 * MAXF];
__device__ __align__(16) __nv_bfloat16 g_w2tlo[256 * MAXF];
__device__ int g_idx64;

// ---------------------------------------------------------------- helpers
__device__ __forceinline__ void split_bf16(float v, __nv_bfloat16& hi, __nv_bfloat16& lo) {
    hi = __float2bfloat16_rn(v);
    lo = __float2bfloat16_rn(v - __bfloat162float(hi));
}

// ---------------------------------------------------------------- prep
// one warp, ballot: int64 data => all odd int32 words zero.
__global__ void detect_kernel(const int* __restrict__ ei, int n_check) {
    int lane = threadIdx.x;
    int nz = 0;
    for (int i = lane; i < n_check; i += 32) nz += (ei[2 * i + 1] != 0);
    unsigned any = __ballot_sync(0xffffffffu, nz != 0);
    if (lane == 0) g_idx64 = (any == 0) ? 1 : 0;
}

__global__ void init_kernel(int* __restrict__ cnt, int* __restrict__ cur, int n) {
    int i = blockIdx.x * blockDim.x + threadIdx.x;
    if (i < n) { cnt[i] = 0; cur[i] = 0; }
}

// blocks [0,eb): degree count. [eb,eb+xb): x split. [.. +w1b): W1 T-split.
// rest: W2 T-split. Everything here has no intra-launch deps.
__global__ void count_split_kernel(const void* __restrict__ eiv, int* __restrict__ cnt,
                                   const float* __restrict__ x,
                                   __nv_bfloat16* __restrict__ xhi,
                                   __nv_bfloat16* __restrict__ xlo,
                                   const float* __restrict__ W1,
                                   __nv_bfloat16* __restrict__ w1thi,
                                   __nv_bfloat16* __restrict__ w1tlo,
                                   const float* __restrict__ W2,
                                   __nv_bfloat16* __restrict__ w2thi,
                                   __nv_bfloat16* __restrict__ w2tlo,
                                   long long E, long long nxf4,
                                   int eb, int xb, int w1b,
                                   int K1, int N1, int N2) {
    if (blockIdx.x < eb) {
        long long i = blockIdx.x * (long long)blockDim.x + threadIdx.x;
        if (i >= E) return;
        int d;
        if (g_idx64) d = (int)((const long long*)eiv)[E + i];
        else         d = ((const int*)eiv)[(size_t)E + i];
        atomicAdd(&cnt[d], 1);
    } else if (blockIdx.x < eb + xb) {
        long long i = (blockIdx.x - eb) * (long long)blockDim.x + threadIdx.x;
        if (i >= nxf4) return;
        float4 v = ((const float4*)x)[i];
        __nv_bfloat16 hx, lx, hy, ly, hz, lz, hw, lw;
        split_bf16(v.x, hx, lx); split_bf16(v.y, hy, ly);
        split_bf16(v.z, hz, lz); split_bf16(v.w, hw, lw);
        __nv_bfloat162* ph = (__nv_bfloat162*)xhi + 2 * i;
        __nv_bfloat162* pl = (__nv_bfloat162*)xlo + 2 * i;
        ph[0] = __nv_bfloat162(hx, hy); ph[1] = __nv_bfloat162(hz, hw);
        pl[0] = __nv_bfloat162(lx, ly); pl[1] = __nv_bfloat162(lz, lw);
    } else if (blockIdx.x < eb + xb + w1b) {
        int e = (blockIdx.x - eb - xb) * blockDim.x + threadIdx.x;
        if (e >= K1 * N1) return;
        int k = e / N1, nn = e % N1;
        __nv_bfloat16 h, l;
        split_bf16(W1[e], h, l);
        w1thi[(size_t)nn * K1 + k] = h;
        w1tlo[(size_t)nn * K1 + k] = l;
    } else {
        int e = (blockIdx.x - eb - xb - w1b) * blockDim.x + threadIdx.x;
        if (e >= K1 * N2) return;
        int k = e / N2, nn = e % N2;
        __nv_bfloat16 h, l;
        split_bf16(W2[e], h, l);
        w2thi[(size_t)nn * K1 + k] = h;
        w2tlo[(size_t)nn * K1 + k] = l;
    }
}

// single-block scan cnt -> off (+dinv). 1024 threads x 20 elems, shfl scans.
#define SCAN_CHUNK 20
__global__ void scan_dinv_kernel(const int* __restrict__ cnt, int* __restrict__ off,
                                 float* __restrict__ dinv, int n) {
    __shared__ int wsum[32];
    __shared__ int wbase[32];
    __shared__ int s_total;
    const int t = threadIdx.x;
    const int lane = t & 31, w = t >> 5;
    const int lo = t * SCAN_CHUNK;
    int vals[SCAN_CHUNK];
    int total = 0;
    const bool act = lo < n;
    const int rem = act ? min(SCAN_CHUNK, n - lo) : 0;
    if (act) {
        if (rem == SCAN_CHUNK) {
#pragma unroll
            for (int i = 0; i < SCAN_CHUNK / 4; i++)
                ((int4*)vals)[i] = ((const int4*)(cnt + lo))[i];
        } else {
#pragma unroll
            for (int i = 0; i < SCAN_CHUNK; i++) vals[i] = (i < rem) ? cnt[lo + i] : 0;
        }
#pragma unroll
        for (int i = 0; i < SCAN_CHUNK; i++) total += vals[i];
    }
    int incl = total;
#pragma unroll
    for (int d = 1; d < 32; d <<= 1) {
        int v = __shfl_up_sync(0xffffffffu, incl, d);
        if (lane >= d) incl += v;
    }
    if (lane == 31) wsum[w] = incl;
    __syncthreads();
    if (w == 0) {
        int v = wsum[lane];
        int iv = v;
#pragma unroll
        for (int d = 1; d < 32; d <<= 1) {
            int u = __shfl_up_sync(0xffffffffu, iv, d);
            if (lane >= d) iv += u;
        }
        wbase[lane] = iv - v;
        if (lane == 31) s_total = iv;
    }
    __syncthreads();
    if (act) {
        int run = wbase[w] + (incl - total);
        int offs[SCAN_CHUNK]; float dv[SCAN_CHUNK];
#pragma unroll
        for (int i = 0; i < SCAN_CHUNK; i++) {
            offs[i] = run;
            dv[i] = rsqrtf((float)vals[i] + 1.0f);
            run += vals[i];
        }
        if (rem == SCAN_CHUNK) {
#pragma unroll
            for (int i = 0; i < SCAN_CHUNK / 4; i++) {
                ((int4*)(off + lo))[i] = ((int4*)offs)[i];
                ((float4*)(dinv + lo))[i] = ((float4*)dv)[i];
            }
        } else {
            for (int i = 0; i < rem; i++) { off[lo + i] = offs[i]; dinv[lo + i] = dv[i]; }
        }
    }
    if (t == 0) off[n] = s_total;
}

// CSR fill only (needs off from scan).
__global__ void fill_kernel(const void* __restrict__ eiv, const int* __restrict__ off,
                            int* __restrict__ cur, int* __restrict__ csr, long long E) {
    long long i = blockIdx.x * (long long)blockDim.x + threadIdx.x;
    if (i >= E) return;
    int s, d;
    if (g_idx64) {
        const long long* ei = (const long long*)eiv;
        s = (int)ei[i]; d = (int)ei[E + i];
    } else {
        const int* ei = (const int*)eiv;
        s = ei[(size_t)i]; d = ei[(size_t)E + i];
    }
    int pos = off[d] + atomicAdd(&cur[d], 1);
    csr[pos] = s;
}

// ---------------------------------------------------------------- HMMA GEMM
// C[M,Ntot] = A[M,K] @ Bt[Ntot,K]^T.  A,Bt given as bf16 hi/lo pairs.
// CTA tile 128x128, BK=32, 8 warps (warp tile 32x64), cp.async double buffer.
// Smem rows padded to 40 bf16 (80 B stride -> conflict-free ldmatrix).

#define SKP 40                     // padded row stride (bf16)
#define TILE_ELE (128 * SKP)       // one 128x32 tile (padded), in bf16
#define STAGE_ELE (4 * TILE_ELE)   // Ahi,Alo,Bhi,Blo
#define GEMM_SMEM_BYTES (2 * STAGE_ELE * 2)

__device__ __forceinline__ uint32_t smem_cast(const void* p) {
    return (uint32_t)__cvta_generic_to_shared(p);
}
__device__ __forceinline__ void cp16(uint32_t dst, const void* src) {
    asm volatile("cp.async.cg.shared.global [%0], [%1], 16;" :: "r"(dst), "l"(src));
}
__device__ __forceinline__ void ldm_x4(uint32_t* r, uint32_t addr) {
    asm volatile("ldmatrix.sync.aligned.m8n8.x4.shared.b16 {%0,%1,%2,%3}, [%4];"
                 : "=r"(r[0]), "=r"(r[1]), "=r"(r[2]), "=r"(r[3]) : "r"(addr));
}
// B fragment: b0 = same-n k0-7, b1 = same-n k8-15 (non-contiguous in ldm regs!)
__device__ __forceinline__ void mma16816(float* c, const uint32_t* a,
                                         uint32_t b0, uint32_t b1) {
    asm volatile(
        "mma.sync.aligned.m16n8k16.row.col.f32.bf16.bf16.f32 "
        "{%0,%1,%2,%3}, {%4,%5,%6,%7}, {%8,%9}, {%0,%1,%2,%3};"
        : "+f"(c[0]), "+f"(c[1]), "+f"(c[2]), "+f"(c[3])
        : "r"(a[0]), "r"(a[1]), "r"(a[2]), "r"(a[3]), "r"(b0), "r"(b1));
}

extern __shared__ __nv_bfloat16 dynsmem[];

__global__ __launch_bounds__(256)
void gemm_tc_kernel(const __nv_bfloat16* __restrict__ Ahi, const __nv_bfloat16* __restrict__ Alo,
                    const __nv_bfloat16* __restrict__ Bhi, const __nv_bfloat16* __restrict__ Blo,
                    float* __restrict__ C, int M, int Ntot, int K) {
    const int tid = threadIdx.x;
    const int wid = tid >> 5;
    const int lane = tid & 31;
    const int m0 = blockIdx.x * 128;
    const int n0 = blockIdx.y * 128;
    const int wm = (wid & 3) * 32;   // warp m offset in tile
    const int wn = (wid >> 2) * 64;  // warp n offset in tile

    float acc[2][8][4];
#pragma unroll
    for (int i = 0; i < 2; i++)
#pragma unroll
        for (int j = 0; j < 8; j++)
#pragma unroll
            for (int q = 0; q < 4; q++) acc[i][j][q] = 0.0f;

    // cp.async issue for stage st (k block ks*32)
    auto issue_stage = [&](int st, int ks) {
        __nv_bfloat16* base = dynsmem + st * STAGE_ELE;
        const int row = tid >> 1;          // 0..127
        const int ch = (tid & 1);
        const long long kofs = (long long)ks * 32;
        int ga = m0 + row; if (ga >= M) ga = M - 1;  // clamp: garbage rows discarded
        const long long aoff = (long long)ga * K + kofs;
        const long long boff = (long long)(n0 + row) * K + kofs;
        uint32_t drow = smem_cast(base) + (row * SKP) * 2;
#pragma unroll
        for (int c = 0; c < 2; c++) {
            int kk = (ch * 2 + c) * 8;
            cp16(drow + kk * 2,                          Ahi + aoff + kk);
            cp16(drow + (TILE_ELE + kk) * 2,             Alo + aoff + kk);
            cp16(drow + (2 * TILE_ELE + kk) * 2,         Bhi + boff + kk);
            cp16(drow + (3 * TILE_ELE + kk) * 2,         Blo + boff + kk);
        }
        asm volatile("cp.async.commit_group;" ::: "memory");
    };

    const int nsteps = K >> 5; // BK = 32
    issue_stage(0, 0);

    for (int s = 0; s < nsteps; s++) {
        if (s + 1 < nsteps) {
            issue_stage((s + 1) & 1, s + 1);
            asm volatile("cp.async.wait_group 1;" ::: "memory");
        } else {
            asm volatile("cp.async.wait_group 0;" ::: "memory");
        }
        __syncthreads();

        __nv_bfloat16* base = dynsmem + (s & 1) * STAGE_ELE;
        const uint32_t sAhi = smem_cast(base);
        const uint32_t sAlo = sAhi + TILE_ELE * 2;
        const uint32_t sBhi = sAhi + 2 * TILE_ELE * 2;
        const uint32_t sBlo = sAhi + 3 * TILE_ELE * 2;

#pragma unroll
        for (int k16 = 0; k16 < 2; k16++) {
            const int kc = k16 * 16 + ((lane >> 4) * 8);   // ldmatrix col
            const int lr = lane & 15;                       // ldmatrix row sel

            uint32_t ahi[2][4], alo[2][4];
#pragma unroll
            for (int mf = 0; mf < 2; mf++) {
                uint32_t off = ((wm + mf * 16 + lr) * SKP + kc) * 2;
                ldm_x4(ahi[mf], sAhi + off);
                ldm_x4(alo[mf], sAlo + off);
            }
#pragma unroll
            for (int nf2 = 0; nf2 < 4; nf2++) {
                uint32_t off = ((wn + nf2 * 16 + lr) * SKP + kc) * 2;
                uint32_t bhi[4], blo[4];
                ldm_x4(bhi, sBhi + off);
                ldm_x4(blo, sBlo + off);
                // r0={n0-7,k0-7} r1={n8-15,k0-7} r2={n0-7,k8-15} r3={n8-15,k8-15}
                // => n0-7 uses (r0,r2); n8-15 uses (r1,r3)
#pragma unroll
                for (int mf = 0; mf < 2; mf++) {
                    mma16816(acc[mf][2 * nf2 + 0], ahi[mf], bhi[0], bhi[2]);
                    mma16816(acc[mf][2 * nf2 + 1], ahi[mf], bhi[1], bhi[3]);
                    mma16816(acc[mf][2 * nf2 + 0], ahi[mf], blo[0], blo[2]);
                    mma16816(acc[mf][2 * nf2 + 1], ahi[mf], blo[1], blo[3]);
                    mma16816(acc[mf][2 * nf2 + 0], alo[mf], bhi[0], bhi[2]);
                    mma16816(acc[mf][2 * nf2 + 1], alo[mf], bhi[1], bhi[3]);
                }
            }
        }
        __syncthreads();
    }

    // epilogue: c{0,1} -> row group, cols 2t..2t+1 ; c{2,3} -> row group+8
    const int group = lane >> 2;
    const int tq = lane & 3;
#pragma unroll
    for (int mf = 0; mf < 2; mf++) {
#pragma unroll
        for (int nf = 0; nf < 8; nf++) {
            int col = n0 + wn + nf * 8 + tq * 2;
            int r0 = m0 + wm + mf * 16 + group;
            if (r0 < M) {
                float2 v = make_float2(acc[mf][nf][0], acc[mf][nf][1]);
                *(float2*)(C + (size_t)r0 * Ntot + col) = v;
            }
            int r1 = r0 + 8;
            if (r1 < M) {
                float2 v = make_float2(acc[mf][nf][2], acc[mf][nf][3]);
                *(float2*)(C + (size_t)r1 * Ntot + col) = v;
            }
        }
    }
}

// ---------------------------------------------------------------- aggregation
// layer-1: out = relu(dinv[d]*(sum + dinv[d]*h[d]) + b), write bf16 hi/lo split.
__global__ void gather_split_kernel(const float* __restrict__ h, const int* __restrict__ csr,
                                    const int* __restrict__ off, const float* __restrict__ dinv,
                                    const float* __restrict__ bias,
                                    __nv_bfloat16* __restrict__ ohi,
                                    __nv_bfloat16* __restrict__ olo, int F) {
    int d = blockIdx.x;
    int c = threadIdx.x;
    float di = dinv[d];
    int e0 = off[d], e1 = off[d + 1];

    float4 acc = ((const float4*)(h + (size_t)d * F))[c];
    acc.x *= di; acc.y *= di; acc.z *= di; acc.w *= di;
    for (int e = e0; e < e1; e++) {
        int s = csr[e];
        float ns = dinv[s];
        float4 v = __ldg((const float4*)(h + (size_t)s * F) + c);
        acc.x += ns * v.x; acc.y += ns * v.y; acc.z += ns * v.z; acc.w += ns * v.w;
    }
    float4 bb = ((const float4*)bias)[c];
    acc.x = fmaxf(acc.x * di + bb.x, 0.f);
    acc.y = fmaxf(acc.y * di + bb.y, 0.f);
    acc.z = fmaxf(acc.z * di + bb.z, 0.f);
    acc.w = fmaxf(acc.w * di + bb.w, 0.f);

    __nv_bfloat16 hx, lx, hy, ly, hz, lz, hw, lw;
    split_bf16(acc.x, hx, lx); split_bf16(acc.y, hy, ly);
    split_bf16(acc.z, hz, lz); split_bf16(acc.w, hw, lw);
    size_t base2 = ((size_t)d * F) / 2 + 2 * c;
    ((__nv_bfloat162*)ohi)[base2 + 0] = __nv_bfloat162(hx, hy);
    ((__nv_bfloat162*)ohi)[base2 + 1] = __nv_bfloat162(hz, hw);
    ((__nv_bfloat162*)olo)[base2 + 0] = __nv_bfloat162(lx, ly);
    ((__nv_bfloat162*)olo)[base2 + 1] = __nv_bfloat162(lz, lw);
}

// layer-2: plain fp32 output
__global__ void gather_kernel(const float* __restrict__ h, const int* __restrict__ csr,
                              const int* __restrict__ off, const float* __restrict__ dinv,
                              const float* __restrict__ bias, float* __restrict__ out, int F) {
    int d = blockIdx.x;
    int c = threadIdx.x;
    float di = dinv[d];
    int e0 = off[d], e1 = off[d + 1];

    float4 acc = ((const float4*)(h + (size_t)d * F))[c];
    acc.x *= di; acc.y *= di; acc.z *= di; acc.w *= di;
    for (int e = e0; e < e1; e++) {
        int s = csr[e];
        float ns = dinv[s];
        float4 v = __ldg((const float4*)(h + (size_t)s * F) + c);
        acc.x += ns * v.x; acc.y += ns * v.y; acc.z += ns * v.z; acc.w += ns * v.w;
    }
    float4 bb = ((const float4*)bias)[c];
    acc.x = fmaxf(acc.x * di + bb.x, 0.f);
    acc.y = fmaxf(acc.y * di + bb.y, 0.f);
    acc.z = fmaxf(acc.z * di + bb.z, 0.f);
    acc.w = fmaxf(acc.w * di + bb.w, 0.f);
    ((float4*)(out + (size_t)d * F))[c] = acc;
}

// ---------------------------------------------------------------- launch
extern "C" void kernel_launch(void* const* d_in, const int* in_sizes, int n_in,
                              void* d_out, int out_size) {
    const float* x  = (const float*)d_in[0];
    const void*  ei = d_in[1];
    const float* W1 = (const float*)d_in[2];
    const float* b1 = (const float*)d_in[3];
    const float* W2 = (const float*)d_in[4];
    const float* b2 = (const float*)d_in[5];
    float* out = (float*)d_out;

    const int hf   = in_sizes[3];                   // 512
    const int inf  = in_sizes[2] / hf;              // 512
    const int ncls = in_sizes[5];                   // 256
    const int n    = in_sizes[0] / inf;             // 20000
    const long long E = (long long)in_sizes[1] / 2; // 160000

    int *p_cnt, *p_cur, *p_off, *p_csr;
    float *p_dinv, *p_h, *p_agg;
    __nv_bfloat16 *p_xhi, *p_xlo, *p_hhi, *p_hlo, *p_w1hi, *p_w1lo, *p_w2hi, *p_w2lo;
    cudaGetSymbolAddress((void**)&p_cnt, g_cnt);
    cudaGetSymbolAddress((void**)&p_cur, g_cursor);
    cudaGetSymbolAddress((void**)&p_off, g_off);
    cudaGetSymbolAddress((void**)&p_csr, g_csr_src);
    cudaGetSymbolAddress((void**)&p_dinv, g_dinv);
    cudaGetSymbolAddress((void**)&p_h, g_h);
    cudaGetSymbolAddress((void**)&p_agg, g_agg);
    cudaGetSymbolAddress((void**)&p_xhi, g_xhi);
    cudaGetSymbolAddress((void**)&p_xlo, g_xlo);
    cudaGetSymbolAddress((void**)&p_hhi, g_hhi);
    cudaGetSymbolAddress((void**)&p_hlo, g_hlo);
    cudaGetSymbolAddress((void**)&p_w1hi, g_w1thi);
    cudaGetSymbolAddress((void**)&p_w1lo, g_w1tlo);
    cudaGetSymbolAddress((void**)&p_w2hi, g_w2thi);
    cudaGetSymbolAddress((void**)&p_w2lo, g_w2tlo);

    cudaFuncSetAttribute(gemm_tc_kernel, cudaFuncAttributeMaxDynamicSharedMemorySize,
                         GEMM_SMEM_BYTES);

    const int eb = (int)((E + 255) / 256);
    const long long nxf4 = (long long)n * inf / 4;
    const int xb = (int)((nxf4 + 255) / 256);
    const int w1b = (inf * hf + 255) / 256;
    const int w2b = (hf * ncls + 255) / 256;

    detect_kernel<<<1, 32>>>((const int*)ei, 256);                             // 1
    init_kernel<<<(n + 255) / 256, 256>>>(p_cnt, p_cur, n);                    // 2
    count_split_kernel<<<eb + xb + w1b + w2b, 256>>>(ei, p_cnt, x, p_xhi, p_xlo,
                                                     W1, p_w1hi, p_w1lo,
                                                     W2, p_w2hi, p_w2lo,
                                                     E, nxf4, eb, xb, w1b,
                                                     inf, hf, ncls);           // 3
    {
        dim3 grid((n + 127) / 128, hf / 128);
        gemm_tc_kernel<<<grid, 256, GEMM_SMEM_BYTES>>>(p_xhi, p_xlo, p_w1hi, p_w1lo,
                                                       p_h, n, hf, inf);       // 4
    }
    scan_dinv_kernel<<<1, 1024>>>(p_cnt, p_off, p_dinv, n);                    // 5
    fill_kernel<<<eb, 256>>>(ei, p_off, p_cur, p_csr, E);                      // 6
    gather_split_kernel<<<n, hf / 4>>>(p_h, p_csr, p_off, p_dinv, b1,
                                       p_hhi, p_hlo, hf);                      // 7
    {
        dim3 grid((n + 127) / 128, ncls / 128);
        gemm_tc_kernel<<<grid, 256, GEMM_SMEM_BYTES>>>(p_hhi, p_hlo, p_w2hi, p_w2lo,
                                                       p_agg, n, ncls, hf);    // 8
    }
    gather_kernel<<<n, ncls / 4>>>(p_agg, p_csr, p_off, p_dinv, b2,
                                   out, ncls);                                 // 9
}